// round 2
// baseline (speedup 1.0000x reference)
#include <cuda_runtime.h>
#include <math.h>

// Problem constants (SPINN1: B=128, T=40, D_HID=512, D_TRK=256)
#define BB   128
#define TT   40
#define DD   512
#define TRK  256
#define CAP  (TT + 2)            // 42
#define TWOD (2 * DD)            // 1024
#define KTRK (3 * DD + TRK)      // 1792  (x = [buf_h | s1_h | s2_h | th])
#define NTRK (4 * TRK)           // 1024
#define KRED (2 * DD + TRK)      // 1280  (xR = [s2_h | s1_h | th_new])
#define NRED (5 * DD)            // 2560

// ---------------- device state (no runtime allocation allowed) --------------
__device__ float g_stack[BB * CAP * TWOD];   // ~22 MB
__device__ float g_th[BB * TRK];
__device__ float g_tc[BB * TRK];
__device__ int   g_sptr[BB];
__device__ int   g_blen[BB];
__device__ float g_xT[BB * KTRK];            // tracker GEMM input
__device__ float g_xR[BB * KRED];            // reduce GEMM input
__device__ float g_gates[BB * NTRK];         // tracker GEMM output (bias-preloaded)
__device__ float g_rin[BB * NRED];           // reduce GEMM output (bias-preloaded)
__device__ int   g_trans[BB];
__device__ float g_Wtrk[NTRK * KTRK];        // [W_ih | W_hh] concat along K, 7.3 MB
__device__ float g_Wred[NRED * KRED];        // [W_left | W_right | W_track], 13.1 MB
__device__ float g_btrk[NTRK];               // b_ih + b_hh

__device__ __forceinline__ float sigf(float x) { return 1.0f / (1.0f + expf(-x)); }

// ---------------- init: concat weights, init stack/state --------------------
__global__ void k_init(const float* __restrict__ buffers,
                       const float* __restrict__ W_ih, const float* __restrict__ W_hh,
                       const float* __restrict__ b_ih, const float* __restrict__ b_hh,
                       const float* __restrict__ W_left, const float* __restrict__ W_right,
                       const float* __restrict__ W_track) {
    int stride = gridDim.x * blockDim.x;
    int tid0 = blockIdx.x * blockDim.x + threadIdx.x;

    for (int idx = tid0; idx < NTRK * KTRK; idx += stride) {
        int n = idx / KTRK, k = idx - n * KTRK;
        g_Wtrk[idx] = (k < 3 * DD) ? W_ih[n * (3 * DD) + k] : W_hh[n * TRK + (k - 3 * DD)];
    }
    for (int idx = tid0; idx < NRED * KRED; idx += stride) {
        int n = idx / KRED, k = idx - n * KRED;
        float v;
        if (k < DD)            v = W_left[n * DD + k];
        else if (k < 2 * DD)   v = W_right[n * DD + (k - DD)];
        else                   v = W_track[n * TRK + (k - 2 * DD)];
        g_Wred[idx] = v;
    }
    for (int idx = tid0; idx < NTRK; idx += stride) g_btrk[idx] = b_ih[idx] + b_hh[idx];
    for (int idx = tid0; idx < BB * TWOD; idx += stride) {
        int b = idx / TWOD, j = idx - b * TWOD;
        float v = buffers[(long)b * TT * TWOD + j];   // buffers[b, 0, j]
        g_stack[((long)b * CAP + 0) * TWOD + j] = v;
        g_stack[((long)b * CAP + 1) * TWOD + j] = v;
    }
    for (int idx = tid0; idx < BB * TRK; idx += stride) { g_th[idx] = 0.f; g_tc[idx] = 0.f; }
    for (int idx = tid0; idx < BB; idx += stride) { g_sptr[idx] = 2; g_blen[idx] = TT; }
}

// ---------------- gather inputs for step 0 ---------------------------------
__global__ void k_prep(const float* __restrict__ buffers, const float* __restrict__ b_left) {
    int b = blockIdx.x, tid = threadIdx.x;
    int sptr = g_sptr[b], blen = g_blen[b];
    const float* bt = buffers + ((long)b * TT + (blen - 1)) * TWOD;
    const float* s1 = g_stack + ((long)b * CAP + (sptr - 1)) * TWOD;
    const float* s2 = g_stack + ((long)b * CAP + (sptr - 2)) * TWOD;
    float* xT = g_xT + b * KTRK;
    float* xR = g_xR + b * KRED;
    for (int j = tid; j < DD; j += blockDim.x) {
        xT[j] = bt[j]; xT[DD + j] = s1[j]; xT[2 * DD + j] = s2[j];
        xR[j] = s2[j]; xR[DD + j] = s1[j];
    }
    for (int j = tid; j < TRK; j += blockDim.x) xT[3 * DD + j] = g_th[b * TRK + j];
    for (int j = tid; j < NTRK; j += blockDim.x) g_gates[b * NTRK + j] = g_btrk[j];
    for (int j = tid; j < NRED; j += blockDim.x) g_rin[b * NRED + j] = b_left[j];
}

// ---------------- split-K fp32 GEMM: C[128,N] += A[128,K] * W[N,K]^T --------
// grid = (N/32, SPLITK), 256 threads. BM=128, BN=32, BK=16, microtile 4x4.
__global__ __launch_bounds__(256) void k_gemm(const float* __restrict__ A,
                                              const float* __restrict__ W,
                                              float* __restrict__ C,
                                              int N, int K, int kChunk) {
    __shared__ float As[16][128];
    __shared__ float Ws[16][32];
    int tid = threadIdx.x;
    int nBase = blockIdx.x * 32;
    int kbase = blockIdx.y * kChunk;
    int tm = (tid & 31) * 4;     // lanes span m -> conflict-free LDS.128
    int tn = (tid >> 5) * 4;     // warp-uniform n -> broadcast
    float acc[4][4] = {};

    for (int k0 = kbase; k0 < kbase + kChunk; k0 += 16) {
        #pragma unroll
        for (int r = 0; r < 2; r++) {
            int qq = tid + r * 256;        // 512 float4 total for A tile
            int row = qq >> 2;
            int kk = (qq & 3) * 4;
            float4 v = *(const float4*)(A + (long)row * K + k0 + kk);
            As[kk + 0][row] = v.x; As[kk + 1][row] = v.y;
            As[kk + 2][row] = v.z; As[kk + 3][row] = v.w;
        }
        if (tid < 128) {                   // 128 float4 for W tile
            int row = tid >> 2;
            int kk = (tid & 3) * 4;
            float4 v = *(const float4*)(W + (long)(nBase + row) * K + k0 + kk);
            Ws[kk + 0][row] = v.x; Ws[kk + 1][row] = v.y;
            Ws[kk + 2][row] = v.z; Ws[kk + 3][row] = v.w;
        }
        __syncthreads();
        #pragma unroll
        for (int kk = 0; kk < 16; kk++) {
            float4 a = *(const float4*)&As[kk][tm];
            float4 w = *(const float4*)&Ws[kk][tn];
            acc[0][0] += a.x * w.x; acc[0][1] += a.x * w.y; acc[0][2] += a.x * w.z; acc[0][3] += a.x * w.w;
            acc[1][0] += a.y * w.x; acc[1][1] += a.y * w.y; acc[1][2] += a.y * w.z; acc[1][3] += a.y * w.w;
            acc[2][0] += a.z * w.x; acc[2][1] += a.z * w.y; acc[2][2] += a.z * w.z; acc[2][3] += a.z * w.w;
            acc[3][0] += a.w * w.x; acc[3][1] += a.w * w.y; acc[3][2] += a.w * w.z; acc[3][3] += a.w * w.w;
        }
        __syncthreads();
    }
    #pragma unroll
    for (int i = 0; i < 4; i++)
        #pragma unroll
        for (int j = 0; j < 4; j++)
            atomicAdd(&C[(long)(tm + i) * N + nBase + tn + j], acc[i][j]);
}

// ---------------- tracker LSTM cell + logits + argmax decision -------------
__global__ void k_cell(const float* __restrict__ W_trans, const float* __restrict__ b_trans,
                       float* __restrict__ out, int step) {
    int b = blockIdx.x, j = threadIdx.x;   // 256 threads
    const float* g = g_gates + b * NTRK;
    float gi = g[j], gf = g[TRK + j], gg = g[2 * TRK + j], go = g[3 * TRK + j];
    float tc = g_tc[b * TRK + j];
    float tcn = sigf(gf) * tc + sigf(gi) * tanhf(gg);
    float thn = sigf(go) * tanhf(tcn);
    g_tc[b * TRK + j] = tcn;
    g_th[b * TRK + j] = thn;
    g_xR[b * KRED + 2 * DD + j] = thn;     // feed reduce GEMM this step

    float p0 = thn * W_trans[0 * TRK + j];
    float p1 = thn * W_trans[1 * TRK + j];
    float p2 = thn * W_trans[2 * TRK + j];
    float p3 = thn * W_trans[3 * TRK + j];
    #pragma unroll
    for (int off = 16; off > 0; off >>= 1) {
        p0 += __shfl_down_sync(0xffffffffu, p0, off);
        p1 += __shfl_down_sync(0xffffffffu, p1, off);
        p2 += __shfl_down_sync(0xffffffffu, p2, off);
        p3 += __shfl_down_sync(0xffffffffu, p3, off);
    }
    __shared__ float sp[4][8];
    if ((j & 31) == 0) {
        int w = j >> 5;
        sp[0][w] = p0; sp[1][w] = p1; sp[2][w] = p2; sp[3][w] = p3;
    }
    __syncthreads();
    if (j == 0) {
        float l[4];
        #pragma unroll
        for (int t = 0; t < 4; t++) {
            float s = b_trans[t];
            #pragma unroll
            for (int w = 0; w < 8; w++) s += sp[t][w];
            l[t] = s;
        }
        float* o = out + ((long)step * BB + b) * 4;
        o[0] = l[0]; o[1] = l[1]; o[2] = l[2]; o[3] = l[3];
        int best = 0; float bv = l[0];                     // jnp.argmax: first max
        if (l[1] > bv) { bv = l[1]; best = 1; }
        if (l[2] > bv) { bv = l[2]; best = 2; }
        if (l[3] > bv) { bv = l[3]; best = 3; }
        g_trans[b] = best;
    }
}

// ---------------- TreeLSTM epilogue + stack update + gather for next -------
__global__ void k_epi(const float* __restrict__ buffers, const float* __restrict__ b_left) {
    int b = blockIdx.x, tid = threadIdx.x;  // 512 threads
    int sptr = g_sptr[b], blen = g_blen[b];
    int tr = g_trans[b];
    bool do_shift = (tr == 3) && (blen > 2);
    bool do_red   = (tr == 2) && (sptr > 3);
    float* st = g_stack + (long)b * CAP * TWOD;
    const float* bt = buffers + ((long)b * TT + (blen - 1)) * TWOD;

    {   // each thread owns one of 512 d-positions
        int dd = tid;
        const float* r = g_rin + b * NRED;
        float a  = r[dd];
        float i_ = r[DD + dd];
        float f1 = r[2 * DD + dd];
        float f2 = r[3 * DD + dd];
        float o_ = r[4 * DD + dd];
        float s2c = st[(sptr - 2) * TWOD + DD + dd];
        float s1c = st[(sptr - 1) * TWOD + DD + dd];
        float c = tanhf(a) * sigf(i_) + sigf(f1) * s2c + sigf(f2) * s1c;
        float h = sigf(o_) * tanhf(c);
        if (do_red) {
            st[(sptr - 2) * TWOD + dd]      = h;
            st[(sptr - 2) * TWOD + DD + dd] = c;
        }
        if (do_shift) {
            st[sptr * TWOD + dd]      = bt[dd];
            st[sptr * TWOD + DD + dd] = bt[DD + dd];
        }
    }
    int nsp = sptr + (do_shift ? 1 : 0) - (do_red ? 1 : 0);
    int nbl = blen - (do_shift ? 1 : 0);
    if (tid == 0) { g_sptr[b] = nsp; g_blen[b] = nbl; }
    __syncthreads();

    // gather inputs for next step
    const float* nbt = buffers + ((long)b * TT + (nbl - 1)) * TWOD;
    const float* s1 = st + (nsp - 1) * TWOD;
    const float* s2 = st + (nsp - 2) * TWOD;
    float* xT = g_xT + b * KTRK;
    float* xR = g_xR + b * KRED;
    for (int j = tid; j < DD; j += blockDim.x) {
        xT[j] = nbt[j]; xT[DD + j] = s1[j]; xT[2 * DD + j] = s2[j];
        xR[j] = s2[j];  xR[DD + j] = s1[j];
    }
    for (int j = tid; j < TRK; j += blockDim.x) xT[3 * DD + j] = g_th[b * TRK + j];
    for (int j = tid; j < NTRK; j += blockDim.x) g_gates[b * NTRK + j] = g_btrk[j];
    for (int j = tid; j < NRED; j += blockDim.x) g_rin[b * NRED + j] = b_left[j];
}

// ---------------------------------------------------------------------------
extern "C" void kernel_launch(void* const* d_in, const int* in_sizes, int n_in,
                              void* d_out, int out_size) {
    const float* buffers = (const float*)d_in[0];
    const float* W_left  = (const float*)d_in[1];
    const float* b_left  = (const float*)d_in[2];
    const float* W_right = (const float*)d_in[3];
    const float* W_track = (const float*)d_in[4];
    const float* W_ih    = (const float*)d_in[5];
    const float* W_hh    = (const float*)d_in[6];
    const float* b_ih    = (const float*)d_in[7];
    const float* b_hh    = (const float*)d_in[8];
    const float* W_trans = (const float*)d_in[9];
    const float* b_trans = (const float*)d_in[10];
    int n_steps = in_sizes[11] / BB;       // transitions: [n_steps, B]
    float* out = (float*)d_out;

    void *pxT, *pxR, *pG, *pR, *pWt, *pWr;
    cudaGetSymbolAddress(&pxT, g_xT);
    cudaGetSymbolAddress(&pxR, g_xR);
    cudaGetSymbolAddress(&pG,  g_gates);
    cudaGetSymbolAddress(&pR,  g_rin);
    cudaGetSymbolAddress(&pWt, g_Wtrk);
    cudaGetSymbolAddress(&pWr, g_Wred);

    k_init<<<592, 256>>>(buffers, W_ih, W_hh, b_ih, b_hh, W_left, W_right, W_track);
    k_prep<<<BB, 256>>>(buffers, b_left);

    for (int s = 0; s < n_steps; s++) {
        // tracker GEMM: M=128, N=1024, K=1792, split-K 4 -> 128 blocks
        k_gemm<<<dim3(NTRK / 32, 4), 256>>>((const float*)pxT, (const float*)pWt,
                                            (float*)pG, NTRK, KTRK, KTRK / 4);
        k_cell<<<BB, 256>>>(W_trans, b_trans, out, s);
        if (s + 1 < n_steps) {
            // reduce GEMM: M=128, N=2560, K=1280, split-K 2 -> 160 blocks
            k_gemm<<<dim3(NRED / 32, 2), 256>>>((const float*)pxR, (const float*)pWr,
                                                (float*)pR, NRED, KRED, KRED / 2);
            k_epi<<<BB, 512>>>(buffers, b_left);
        }
    }
}

// round 3
// speedup vs baseline: 1.7783x; 1.7783x over previous
#include <cuda_runtime.h>
#include <math.h>

// Problem constants (SPINN1: B=128, T=40, D_HID=512, D_TRK=256)
#define BB   128
#define TT   40
#define DD   512
#define TRK  256
#define CAP  (TT + 2)            // 42
#define TWOD (2 * DD)            // 1024
#define KTRK (3 * DD + TRK)      // 1792  (x = [buf_h | s1_h | s2_h | th])
#define NTRK (4 * TRK)           // 1024
#define KRED (2 * DD + TRK)      // 1280  (xR = [s2_h | s1_h | th_new])
#define NRED (5 * DD)            // 2560
#define SPLIT_T 16               // tracker split-K (7 slabs of 16 each)
#define SPLIT_R 7                // reduce split-K  (12,12,12,12,12,12,8 slabs)

// ---------------- device state (no runtime allocation allowed) --------------
__device__ float g_stack[BB * CAP * TWOD];   // ~22 MB
__device__ float g_th[BB * TRK];
__device__ float g_tc[BB * TRK];
__device__ int   g_sptr[BB];
__device__ int   g_blen[BB];
__device__ float g_xT[BB * KTRK];            // tracker GEMM input
__device__ float g_xR[BB * KRED];            // reduce GEMM input
__device__ float g_partT[SPLIT_T * BB * NTRK];   // 8 MB split-K partials
__device__ float g_partR[SPLIT_R * BB * NRED];   // 9.2 MB
__device__ int   g_trans[BB];
__device__ float g_Wtrk[NTRK * KTRK];        // [W_ih | W_hh] concat along K
__device__ float g_Wred[NRED * KRED];        // [W_left | W_right | W_track]
__device__ float g_btrk[NTRK];               // b_ih + b_hh

__device__ __forceinline__ float sigf(float x) { return 1.0f / (1.0f + expf(-x)); }

typedef unsigned long long ull;
__device__ __forceinline__ ull packf2(float x, float y) {
    ull v; asm("mov.b64 %0, {%1,%2};" : "=l"(v) : "f"(x), "f"(y)); return v;
}
__device__ __forceinline__ float2 unpackf2(ull v) {
    float2 r; asm("mov.b64 {%0,%1}, %2;" : "=f"(r.x), "=f"(r.y) : "l"(v)); return r;
}
__device__ __forceinline__ void ffma2(ull& d, ull a, ull b) {
    asm("fma.rn.f32x2 %0, %1, %2, %0;" : "+l"(d) : "l"(a), "l"(b));
}

// ---------------- init: concat weights, init stack/state --------------------
__global__ void k_init(const float* __restrict__ buffers,
                       const float* __restrict__ W_ih, const float* __restrict__ W_hh,
                       const float* __restrict__ b_ih, const float* __restrict__ b_hh,
                       const float* __restrict__ W_left, const float* __restrict__ W_right,
                       const float* __restrict__ W_track) {
    int stride = gridDim.x * blockDim.x;
    int tid0 = blockIdx.x * blockDim.x + threadIdx.x;

    for (int idx = tid0; idx < NTRK * KTRK; idx += stride) {
        int n = idx / KTRK, k = idx - n * KTRK;
        g_Wtrk[idx] = (k < 3 * DD) ? W_ih[n * (3 * DD) + k] : W_hh[n * TRK + (k - 3 * DD)];
    }
    for (int idx = tid0; idx < NRED * KRED; idx += stride) {
        int n = idx / KRED, k = idx - n * KRED;
        float v;
        if (k < DD)            v = W_left[n * DD + k];
        else if (k < 2 * DD)   v = W_right[n * DD + (k - DD)];
        else                   v = W_track[n * TRK + (k - 2 * DD)];
        g_Wred[idx] = v;
    }
    for (int idx = tid0; idx < NTRK; idx += stride) g_btrk[idx] = b_ih[idx] + b_hh[idx];
    for (int idx = tid0; idx < BB * TWOD; idx += stride) {
        int b = idx / TWOD, j = idx - b * TWOD;
        float v = buffers[(long)b * TT * TWOD + j];   // buffers[b, 0, j]
        g_stack[((long)b * CAP + 0) * TWOD + j] = v;
        g_stack[((long)b * CAP + 1) * TWOD + j] = v;
    }
    for (int idx = tid0; idx < BB * TRK; idx += stride) { g_th[idx] = 0.f; g_tc[idx] = 0.f; }
    for (int idx = tid0; idx < BB; idx += stride) { g_sptr[idx] = 2; g_blen[idx] = TT; }
}

// ---------------- gather inputs for step 0 ---------------------------------
__global__ void k_prep(const float* __restrict__ buffers) {
    int b = blockIdx.x, tid = threadIdx.x;
    int sptr = g_sptr[b], blen = g_blen[b];
    const float* bt = buffers + ((long)b * TT + (blen - 1)) * TWOD;
    const float* s1 = g_stack + ((long)b * CAP + (sptr - 1)) * TWOD;
    const float* s2 = g_stack + ((long)b * CAP + (sptr - 2)) * TWOD;
    float* xT = g_xT + b * KTRK;
    float* xR = g_xR + b * KRED;
    for (int j = tid; j < DD; j += blockDim.x) {
        xT[j] = bt[j]; xT[DD + j] = s1[j]; xT[2 * DD + j] = s2[j];
        xR[j] = s2[j]; xR[DD + j] = s1[j];
    }
    for (int j = tid; j < TRK; j += blockDim.x) xT[3 * DD + j] = g_th[b * TRK + j];
}

// ---------------- split-K fp32x2 GEMM: Cpart[s] = A[128,Kslab] * W^T slab ---
// grid = (N/128, SPLITK), 256 threads. BM=128, BN=128, BK=16, microtile 8x8,
// fma.rn.f32x2 packed accumulation, double-buffered smem, 1 sync/slab.
__global__ __launch_bounds__(256) void k_gemm(const float* __restrict__ A,
                                              const float* __restrict__ W,
                                              float* __restrict__ Cpart,
                                              int N, int K, int chunkIters) {
    __shared__ float As[2][16][128];
    __shared__ float Ws[2][16][128];
    int tid = threadIdx.x;
    int nBase = blockIdx.x * 128;
    int kBase = blockIdx.y * chunkIters * 16;
    int iters = (K - kBase) / 16;
    if (iters > chunkIters) iters = chunkIters;

    int tm = (tid & 15) * 8;     // 8 m-rows per thread
    int tn = (tid >> 4) * 8;     // 8 n-cols per thread
    // loader mapping: each thread owns 2 float4 of A-tile and 2 of W-tile
    int lrow0 = tid >> 2;              // rows 0..63
    int lrow1 = lrow0 + 64;            // rows 64..127
    int lk    = (tid & 3) * 4;         // k-group within the 16-slab

    ull acc[32];
    #pragma unroll
    for (int i = 0; i < 32; i++) acc[i] = 0ull;

    // preload slab 0 into buffer 0
    {
        float4 a0 = *(const float4*)(A + (long)lrow0 * K + kBase + lk);
        float4 a1 = *(const float4*)(A + (long)lrow1 * K + kBase + lk);
        float4 w0 = *(const float4*)(W + (long)(nBase + lrow0) * K + kBase + lk);
        float4 w1 = *(const float4*)(W + (long)(nBase + lrow1) * K + kBase + lk);
        As[0][lk + 0][lrow0] = a0.x; As[0][lk + 1][lrow0] = a0.y;
        As[0][lk + 2][lrow0] = a0.z; As[0][lk + 3][lrow0] = a0.w;
        As[0][lk + 0][lrow1] = a1.x; As[0][lk + 1][lrow1] = a1.y;
        As[0][lk + 2][lrow1] = a1.z; As[0][lk + 3][lrow1] = a1.w;
        Ws[0][lk + 0][lrow0] = w0.x; Ws[0][lk + 1][lrow0] = w0.y;
        Ws[0][lk + 2][lrow0] = w0.z; Ws[0][lk + 3][lrow0] = w0.w;
        Ws[0][lk + 0][lrow1] = w1.x; Ws[0][lk + 1][lrow1] = w1.y;
        Ws[0][lk + 2][lrow1] = w1.z; Ws[0][lk + 3][lrow1] = w1.w;
    }
    __syncthreads();

    for (int it = 0; it < iters; it++) {
        int buf = it & 1;
        float4 pa0, pa1, pw0, pw1;
        bool more = (it + 1) < iters;
        if (more) {
            int k0 = kBase + (it + 1) * 16;
            pa0 = *(const float4*)(A + (long)lrow0 * K + k0 + lk);
            pa1 = *(const float4*)(A + (long)lrow1 * K + k0 + lk);
            pw0 = *(const float4*)(W + (long)(nBase + lrow0) * K + k0 + lk);
            pw1 = *(const float4*)(W + (long)(nBase + lrow1) * K + k0 + lk);
        }
        #pragma unroll
        for (int kk = 0; kk < 16; kk++) {
            float4 a0 = *(const float4*)&As[buf][kk][tm];
            float4 a1 = *(const float4*)&As[buf][kk][tm + 4];
            float4 w0 = *(const float4*)&Ws[buf][kk][tn];
            float4 w1 = *(const float4*)&Ws[buf][kk][tn + 4];
            ull wp0 = packf2(w0.x, w0.y);
            ull wp1 = packf2(w0.z, w0.w);
            ull wp2 = packf2(w1.x, w1.y);
            ull wp3 = packf2(w1.z, w1.w);
            float am[8] = {a0.x, a0.y, a0.z, a0.w, a1.x, a1.y, a1.z, a1.w};
            #pragma unroll
            for (int i = 0; i < 8; i++) {
                ull ad = packf2(am[i], am[i]);
                ffma2(acc[i * 4 + 0], ad, wp0);
                ffma2(acc[i * 4 + 1], ad, wp1);
                ffma2(acc[i * 4 + 2], ad, wp2);
                ffma2(acc[i * 4 + 3], ad, wp3);
            }
        }
        if (more) {
            int nb = buf ^ 1;
            As[nb][lk + 0][lrow0] = pa0.x; As[nb][lk + 1][lrow0] = pa0.y;
            As[nb][lk + 2][lrow0] = pa0.z; As[nb][lk + 3][lrow0] = pa0.w;
            As[nb][lk + 0][lrow1] = pa1.x; As[nb][lk + 1][lrow1] = pa1.y;
            As[nb][lk + 2][lrow1] = pa1.z; As[nb][lk + 3][lrow1] = pa1.w;
            Ws[nb][lk + 0][lrow0] = pw0.x; Ws[nb][lk + 1][lrow0] = pw0.y;
            Ws[nb][lk + 2][lrow0] = pw0.z; Ws[nb][lk + 3][lrow0] = pw0.w;
            Ws[nb][lk + 0][lrow1] = pw1.x; Ws[nb][lk + 1][lrow1] = pw1.y;
            Ws[nb][lk + 2][lrow1] = pw1.z; Ws[nb][lk + 3][lrow1] = pw1.w;
            __syncthreads();
        }
    }

    float* Cp = Cpart + (size_t)blockIdx.y * BB * N;
    #pragma unroll
    for (int i = 0; i < 8; i++) {
        float2 v0 = unpackf2(acc[i * 4 + 0]);
        float2 v1 = unpackf2(acc[i * 4 + 1]);
        float2 v2 = unpackf2(acc[i * 4 + 2]);
        float2 v3 = unpackf2(acc[i * 4 + 3]);
        float* row = Cp + (long)(tm + i) * N + nBase + tn;
        *(float4*)(row)     = make_float4(v0.x, v0.y, v1.x, v1.y);
        *(float4*)(row + 4) = make_float4(v2.x, v2.y, v3.x, v3.y);
    }
}

// ---------------- tracker LSTM cell + logits + argmax decision -------------
// Sums the SPLIT_T partials (+bias) inline.
__global__ void k_cell(const float* __restrict__ W_trans, const float* __restrict__ b_trans,
                       float* __restrict__ out, int step) {
    int b = blockIdx.x, j = threadIdx.x;   // 256 threads
    float gi = g_btrk[0 * TRK + j], gf = g_btrk[1 * TRK + j];
    float gg = g_btrk[2 * TRK + j], go = g_btrk[3 * TRK + j];
    #pragma unroll
    for (int s = 0; s < SPLIT_T; s++) {
        const float* p = g_partT + ((size_t)s * BB + b) * NTRK;
        gi += p[0 * TRK + j]; gf += p[1 * TRK + j];
        gg += p[2 * TRK + j]; go += p[3 * TRK + j];
    }
    float tc = g_tc[b * TRK + j];
    float tcn = sigf(gf) * tc + sigf(gi) * tanhf(gg);
    float thn = sigf(go) * tanhf(tcn);
    g_tc[b * TRK + j] = tcn;
    g_th[b * TRK + j] = thn;
    g_xR[b * KRED + 2 * DD + j] = thn;     // feed reduce GEMM this step

    float p0 = thn * W_trans[0 * TRK + j];
    float p1 = thn * W_trans[1 * TRK + j];
    float p2 = thn * W_trans[2 * TRK + j];
    float p3 = thn * W_trans[3 * TRK + j];
    #pragma unroll
    for (int off = 16; off > 0; off >>= 1) {
        p0 += __shfl_down_sync(0xffffffffu, p0, off);
        p1 += __shfl_down_sync(0xffffffffu, p1, off);
        p2 += __shfl_down_sync(0xffffffffu, p2, off);
        p3 += __shfl_down_sync(0xffffffffu, p3, off);
    }
    __shared__ float sp[4][8];
    if ((j & 31) == 0) {
        int w = j >> 5;
        sp[0][w] = p0; sp[1][w] = p1; sp[2][w] = p2; sp[3][w] = p3;
    }
    __syncthreads();
    if (j == 0) {
        float l[4];
        #pragma unroll
        for (int t = 0; t < 4; t++) {
            float s = b_trans[t];
            #pragma unroll
            for (int w = 0; w < 8; w++) s += sp[t][w];
            l[t] = s;
        }
        float* o = out + ((long)step * BB + b) * 4;
        o[0] = l[0]; o[1] = l[1]; o[2] = l[2]; o[3] = l[3];
        int best = 0; float bv = l[0];                     // jnp.argmax: first max
        if (l[1] > bv) { bv = l[1]; best = 1; }
        if (l[2] > bv) { bv = l[2]; best = 2; }
        if (l[3] > bv) { bv = l[3]; best = 3; }
        g_trans[b] = best;
    }
}

// ---------------- TreeLSTM epilogue + stack update + gather for next -------
// Sums the SPLIT_R partials (+b_left) inline.
__global__ void k_epi(const float* __restrict__ buffers, const float* __restrict__ b_left) {
    int b = blockIdx.x, tid = threadIdx.x;  // 512 threads
    int sptr = g_sptr[b], blen = g_blen[b];
    int tr = g_trans[b];
    bool do_shift = (tr == 3) && (blen > 2);
    bool do_red   = (tr == 2) && (sptr > 3);
    float* st = g_stack + (long)b * CAP * TWOD;
    const float* bt = buffers + ((long)b * TT + (blen - 1)) * TWOD;

    {   // each thread owns one of 512 d-positions
        int dd = tid;
        float a  = b_left[dd];
        float i_ = b_left[DD + dd];
        float f1 = b_left[2 * DD + dd];
        float f2 = b_left[3 * DD + dd];
        float o_ = b_left[4 * DD + dd];
        #pragma unroll
        for (int s = 0; s < SPLIT_R; s++) {
            const float* p = g_partR + ((size_t)s * BB + b) * NRED;
            a  += p[dd];
            i_ += p[DD + dd];
            f1 += p[2 * DD + dd];
            f2 += p[3 * DD + dd];
            o_ += p[4 * DD + dd];
        }
        float s2c = st[(sptr - 2) * TWOD + DD + dd];
        float s1c = st[(sptr - 1) * TWOD + DD + dd];
        float c = tanhf(a) * sigf(i_) + sigf(f1) * s2c + sigf(f2) * s1c;
        float h = sigf(o_) * tanhf(c);
        if (do_red) {
            st[(sptr - 2) * TWOD + dd]      = h;
            st[(sptr - 2) * TWOD + DD + dd] = c;
        }
        if (do_shift) {
            st[sptr * TWOD + dd]      = bt[dd];
            st[sptr * TWOD + DD + dd] = bt[DD + dd];
        }
    }
    int nsp = sptr + (do_shift ? 1 : 0) - (do_red ? 1 : 0);
    int nbl = blen - (do_shift ? 1 : 0);
    if (tid == 0) { g_sptr[b] = nsp; g_blen[b] = nbl; }
    __syncthreads();

    // gather inputs for next step
    const float* nbt = buffers + ((long)b * TT + (nbl - 1)) * TWOD;
    const float* s1 = st + (nsp - 1) * TWOD;
    const float* s2 = st + (nsp - 2) * TWOD;
    float* xT = g_xT + b * KTRK;
    float* xR = g_xR + b * KRED;
    for (int j = tid; j < DD; j += blockDim.x) {
        xT[j] = nbt[j]; xT[DD + j] = s1[j]; xT[2 * DD + j] = s2[j];
        xR[j] = s2[j];  xR[DD + j] = s1[j];
    }
    for (int j = tid; j < TRK; j += blockDim.x) xT[3 * DD + j] = g_th[b * TRK + j];
}

// ---------------------------------------------------------------------------
extern "C" void kernel_launch(void* const* d_in, const int* in_sizes, int n_in,
                              void* d_out, int out_size) {
    const float* buffers = (const float*)d_in[0];
    const float* W_left  = (const float*)d_in[1];
    const float* b_left  = (const float*)d_in[2];
    const float* W_right = (const float*)d_in[3];
    const float* W_track = (const float*)d_in[4];
    const float* W_ih    = (const float*)d_in[5];
    const float* W_hh    = (const float*)d_in[6];
    const float* b_ih    = (const float*)d_in[7];
    const float* b_hh    = (const float*)d_in[8];
    const float* W_trans = (const float*)d_in[9];
    const float* b_trans = (const float*)d_in[10];
    int n_steps = in_sizes[11] / BB;       // transitions: [n_steps, B]
    float* out = (float*)d_out;

    void *pxT, *pxR, *pPT, *pPR, *pWt, *pWr;
    cudaGetSymbolAddress(&pxT, g_xT);
    cudaGetSymbolAddress(&pxR, g_xR);
    cudaGetSymbolAddress(&pPT, g_partT);
    cudaGetSymbolAddress(&pPR, g_partR);
    cudaGetSymbolAddress(&pWt, g_Wtrk);
    cudaGetSymbolAddress(&pWr, g_Wred);

    k_init<<<592, 256>>>(buffers, W_ih, W_hh, b_ih, b_hh, W_left, W_right, W_track);
    k_prep<<<BB, 256>>>(buffers);

    for (int s = 0; s < n_steps; s++) {
        // tracker GEMM: M=128, N=1024, K=1792 -> grid (8,16), 7 slabs each
        k_gemm<<<dim3(NTRK / 128, SPLIT_T), 256>>>((const float*)pxT, (const float*)pWt,
                                                   (float*)pPT, NTRK, KTRK, 7);
        k_cell<<<BB, 256>>>(W_trans, b_trans, out, s);
        if (s + 1 < n_steps) {
            // reduce GEMM: M=128, N=2560, K=1280 -> grid (20,7), slabs 12 (last 8)
            k_gemm<<<dim3(NRED / 128, SPLIT_R), 256>>>((const float*)pxR, (const float*)pWr,
                                                       (float*)pPR, NRED, KRED, 12);
            k_epi<<<BB, 512>>>(buffers, b_left);
        }
    }
}